// round 7
// baseline (speedup 1.0000x reference)
#include <cuda_runtime.h>
#include <math.h>

// Problem constants (fixed by setup_inputs)
#define BDIM 8
#define LDIM 1900
#define EDIM 256
#define HDIM 8
#define DDIM 32
#define MROWS (BDIM * LDIM)   // 15200
#define QKVW  (3 * EDIM)      // 768
#define PADSZ 1000
#define GRPW  200             // 2 * single_pad

// Scratch (static device globals; no cudaMalloc allowed)
__device__ float g_qkv[(size_t)MROWS * QKVW];   // 46.7 MB
__device__ float g_ctx[(size_t)MROWS * EDIM];   // 15.6 MB
__device__ float g_y  [(size_t)MROWS * EDIM];   // 15.6 MB

// ---------------------------------------------------------------------------
// Generic tiled SGEMM:  C[m,n] = sum_k A[m,k] * Bw[n,k] + bias[n] (+ resid[m,n])
// BM=BN=64, BK=32, 256 threads, 4x4 per thread.
// ---------------------------------------------------------------------------
template <bool RESID>
__global__ __launch_bounds__(256)
void gemm_bias_kernel(const float* __restrict__ A,
                      const float* __restrict__ Bw,
                      const float* __restrict__ bias,
                      const float* __restrict__ resid,
                      float* __restrict__ C,
                      int M, int N, int K)
{
    __shared__ float As[32][65];   // +1 pad: conflict-free transposed stores
    __shared__ float Bs[32][68];   // +4 pad: keeps rows 16B-aligned for float4

    const int tid = threadIdx.x;
    const int tx  = tid & 15;      // 0..15 -> n
    const int ty  = tid >> 4;      // 0..15 -> m
    const int m0  = blockIdx.y * 64;
    const int n0  = blockIdx.x * 64;

    float acc[4][4];
#pragma unroll
    for (int i = 0; i < 4; ++i)
#pragma unroll
        for (int j = 0; j < 4; ++j) acc[i][j] = 0.f;

    for (int k0 = 0; k0 < K; k0 += 32) {
        // Load A tile (64 x 32), transpose into As[k][m]
#pragma unroll
        for (int it = 0; it < 2; ++it) {
            int flat = tid + it * 256;           // 0..511
            int row  = flat >> 3;                // 0..63
            int k4   = (flat & 7) << 2;          // 0,4,...,28
            float4 v = make_float4(0.f, 0.f, 0.f, 0.f);
            if (m0 + row < M)
                v = *(const float4*)&A[(size_t)(m0 + row) * K + k0 + k4];
            As[k4 + 0][row] = v.x;
            As[k4 + 1][row] = v.y;
            As[k4 + 2][row] = v.z;
            As[k4 + 3][row] = v.w;
        }
        // Load B tile (64 x 32), transpose into Bs[k][n]  (N is multiple of 64)
#pragma unroll
        for (int it = 0; it < 2; ++it) {
            int flat = tid + it * 256;
            int row  = flat >> 3;
            int k4   = (flat & 7) << 2;
            float4 v = *(const float4*)&Bw[(size_t)(n0 + row) * K + k0 + k4];
            Bs[k4 + 0][row] = v.x;
            Bs[k4 + 1][row] = v.y;
            Bs[k4 + 2][row] = v.z;
            Bs[k4 + 3][row] = v.w;
        }
        __syncthreads();

#pragma unroll
        for (int k = 0; k < 32; ++k) {
            float a0 = As[k][ty * 4 + 0];
            float a1 = As[k][ty * 4 + 1];
            float a2 = As[k][ty * 4 + 2];
            float a3 = As[k][ty * 4 + 3];
            float4 bv = *(const float4*)&Bs[k][tx * 4];
            acc[0][0] += a0 * bv.x; acc[0][1] += a0 * bv.y; acc[0][2] += a0 * bv.z; acc[0][3] += a0 * bv.w;
            acc[1][0] += a1 * bv.x; acc[1][1] += a1 * bv.y; acc[1][2] += a1 * bv.z; acc[1][3] += a1 * bv.w;
            acc[2][0] += a2 * bv.x; acc[2][1] += a2 * bv.y; acc[2][2] += a2 * bv.z; acc[2][3] += a2 * bv.w;
            acc[3][0] += a3 * bv.x; acc[3][1] += a3 * bv.y; acc[3][2] += a3 * bv.z; acc[3][3] += a3 * bv.w;
        }
        __syncthreads();
    }

#pragma unroll
    for (int i = 0; i < 4; ++i) {
        int m = m0 + ty * 4 + i;
        if (m >= M) continue;
#pragma unroll
        for (int j = 0; j < 4; ++j) {
            int n = n0 + tx * 4 + j;
            float v = acc[i][j] + bias[n];
            if (RESID) v += resid[(size_t)m * N + n];
            C[(size_t)m * N + n] = v;
        }
    }
}

// ---------------------------------------------------------------------------
// Flash attention with DN mask. One thread = one query row.
// Visible columns per row l:
//   l <  1000 : [g*200, g*200+200)  (g = l/200)   plus  [1000, 1900)
//   l >= 1000 : [1000, 1900)
// ---------------------------------------------------------------------------
__global__ __launch_bounds__(128)
void attn_kernel(const float* __restrict__ qkv, float* __restrict__ ctx)
{
    const int tile = blockIdx.x;                  // 0..14
    const int h    = blockIdx.y;
    const int b    = blockIdx.z;
    const int tid  = threadIdx.x;                 // 128
    const int l    = tile * 128 + tid;
    const bool valid = (l < LDIM);

    __shared__ float Qs[128][DDIM + 1];           // padded: per-thread row reads
    __shared__ float Ks[64][DDIM];                // broadcast reads (no pad)
    __shared__ float Vs[64][DDIM];

    const size_t baseQ = (size_t)b * LDIM * QKVW + (size_t)h * DDIM;
    const size_t baseK = baseQ + EDIM;
    const size_t baseV = baseQ + 2 * EDIM;

    // Coalesced staging of the Q tile, then pull own row to registers
    for (int i = tid; i < 128 * DDIM; i += 128) {
        int r = i >> 5, c = i & 31;
        int lr = tile * 128 + r;
        Qs[r][c] = (lr < LDIM) ? qkv[baseQ + (size_t)lr * QKVW + c] : 0.f;
    }
    __syncthreads();

    float q[DDIM];
#pragma unroll
    for (int i = 0; i < DDIM; ++i) q[i] = Qs[tid][i];

    float o[DDIM];
#pragma unroll
    for (int i = 0; i < DDIM; ++i) o[i] = 0.f;
    float mrow = -3.0e38f;
    float lsum = 0.f;
    const float scale = 0.17677669529663689f;     // 1/sqrt(32)

    // Block-level DN column range (union over rows in this tile)
    const int l0   = tile * 128;
    const int lmx  = (l0 + 127 < LDIM - 1) ? (l0 + 127) : (LDIM - 1);
    int Astart = 0, Aend = 0;
    if (l0 < PADSZ) {
        int gmin = l0 / GRPW;
        int gmax = ((lmx < PADSZ - 1) ? lmx : (PADSZ - 1)) / GRPW;
        Astart = gmin * GRPW;
        Aend   = (gmax + 1) * GRPW;               // <= 1000
    }
    const int myglo = (l / GRPW) * GRPW;          // meaningful only when l < 1000

#pragma unroll 1
    for (int pass = 0; pass < 2; ++pass) {
        const int cs = (pass == 0) ? Astart : PADSZ;
        const int ce = (pass == 0) ? Aend   : LDIM;
#pragma unroll 1
        for (int m0c = cs; m0c < ce; m0c += 64) {
            const int cols = (ce - m0c < 64) ? (ce - m0c) : 64;
            __syncthreads();
            for (int i = tid; i < cols * DDIM; i += 128) {
                int r = i >> 5, c = i & 31;
                size_t off = (size_t)(m0c + r) * QKVW + c;
                Ks[r][c] = qkv[baseK + off];
                Vs[r][c] = qkv[baseV + off];
            }
            __syncthreads();

            if (valid) {
                int jlo = 0, jhi = cols;
                if (pass == 0) {
                    if (l >= PADSZ) {
                        jhi = 0;
                    } else {
                        int a = myglo - m0c;             if (a > 0) jlo = a;
                        int bnd = myglo + GRPW - m0c;    if (bnd < jhi) jhi = bnd;
                    }
                }
                for (int j = jlo; j < jhi; ++j) {
                    const float4* kp = (const float4*)&Ks[j][0];
                    float s0 = 0.f, s1 = 0.f, s2 = 0.f, s3 = 0.f;
#pragma unroll
                    for (int t = 0; t < 8; ++t) {
                        float4 kk = kp[t];
                        s0 += q[4 * t + 0] * kk.x;
                        s1 += q[4 * t + 1] * kk.y;
                        s2 += q[4 * t + 2] * kk.z;
                        s3 += q[4 * t + 3] * kk.w;
                    }
                    float s = ((s0 + s1) + (s2 + s3)) * scale;

                    if (s > mrow) {
                        float corr = __expf(mrow - s);
                        lsum *= corr;
#pragma unroll
                        for (int t = 0; t < DDIM; ++t) o[t] *= corr;
                        mrow = s;
                    }
                    float p = __expf(s - mrow);
                    lsum += p;
                    const float4* vp = (const float4*)&Vs[j][0];
#pragma unroll
                    for (int t = 0; t < 8; ++t) {
                        float4 vv = vp[t];
                        o[4 * t + 0] += p * vv.x;
                        o[4 * t + 1] += p * vv.y;
                        o[4 * t + 2] += p * vv.z;
                        o[4 * t + 3] += p * vv.w;
                    }
                }
            }
        }
    }

    // Normalize and write out (staged through SMEM for coalescing)
    const float inv = valid ? (1.f / lsum) : 0.f;
    __syncthreads();
#pragma unroll
    for (int i = 0; i < DDIM; ++i) Qs[tid][i] = o[i] * inv;
    __syncthreads();
    for (int i = tid; i < 128 * DDIM; i += 128) {
        int r = i >> 5, c = i & 31;
        int lr = tile * 128 + r;
        if (lr < LDIM)
            ctx[((size_t)b * LDIM + lr) * EDIM + (size_t)h * DDIM + c] = Qs[r][c];
    }
}

// ---------------------------------------------------------------------------
// LayerNorm: one warp per row of 256.
// ---------------------------------------------------------------------------
__global__ __launch_bounds__(256)
void ln_kernel(const float* __restrict__ y,
               const float* __restrict__ g,
               const float* __restrict__ bt,
               float* __restrict__ out)
{
    const int row  = blockIdx.x * 8 + (threadIdx.x >> 5);
    const int lane = threadIdx.x & 31;
    if (row >= MROWS) return;

    const float* yr = y + (size_t)row * EDIM;
    float4 v0 = ((const float4*)yr)[lane];
    float4 v1 = ((const float4*)yr)[lane + 32];

    float s  = v0.x + v0.y + v0.z + v0.w + v1.x + v1.y + v1.z + v1.w;
    float ss = v0.x * v0.x + v0.y * v0.y + v0.z * v0.z + v0.w * v0.w
             + v1.x * v1.x + v1.y * v1.y + v1.z * v1.z + v1.w * v1.w;
#pragma unroll
    for (int off = 16; off; off >>= 1) {
        s  += __shfl_xor_sync(0xFFFFFFFFu, s,  off);
        ss += __shfl_xor_sync(0xFFFFFFFFu, ss, off);
    }
    const float mu  = s * (1.f / EDIM);
    const float var = ss * (1.f / EDIM) - mu * mu;
    const float r   = rsqrtf(var + 1e-5f);

    float* orow = out + (size_t)row * EDIM;
    int c0 = lane * 4;
    int c1 = 128 + lane * 4;
    float4 g0 = ((const float4*)g)[lane];
    float4 g1 = ((const float4*)g)[lane + 32];
    float4 b0 = ((const float4*)bt)[lane];
    float4 b1 = ((const float4*)bt)[lane + 32];

    float4 o0, o1;
    o0.x = (v0.x - mu) * r * g0.x + b0.x;
    o0.y = (v0.y - mu) * r * g0.y + b0.y;
    o0.z = (v0.z - mu) * r * g0.z + b0.z;
    o0.w = (v0.w - mu) * r * g0.w + b0.w;
    o1.x = (v1.x - mu) * r * g1.x + b1.x;
    o1.y = (v1.y - mu) * r * g1.y + b1.y;
    o1.z = (v1.z - mu) * r * g1.z + b1.z;
    o1.w = (v1.w - mu) * r * g1.w + b1.w;
    *(float4*)&orow[c0] = o0;
    *(float4*)&orow[c1] = o1;
}

// ---------------------------------------------------------------------------
extern "C" void kernel_launch(void* const* d_in, const int* in_sizes, int n_in,
                              void* d_out, int out_size)
{
    const float* x     = (const float*)d_in[0];
    const float* in_w  = (const float*)d_in[1];
    const float* in_b  = (const float*)d_in[2];
    const float* out_w = (const float*)d_in[3];
    const float* out_b = (const float*)d_in[4];
    const float* ln_g  = (const float*)d_in[5];
    const float* ln_b  = (const float*)d_in[6];
    float* out = (float*)d_out;

    void *p_qkv = nullptr, *p_ctx = nullptr, *p_y = nullptr;
    cudaGetSymbolAddress(&p_qkv, g_qkv);
    cudaGetSymbolAddress(&p_ctx, g_ctx);
    cudaGetSymbolAddress(&p_y,   g_y);
    float* qkv = (float*)p_qkv;
    float* ctx = (float*)p_ctx;
    float* yy  = (float*)p_y;

    // 1) QKV projection: [15200,256] x [768,256]^T -> [15200,768]
    {
        dim3 grid(QKVW / 64, (MROWS + 63) / 64);
        gemm_bias_kernel<false><<<grid, 256>>>(x, in_w, in_b, nullptr, qkv,
                                               MROWS, QKVW, EDIM);
    }
    // 2) Masked flash attention -> ctx [15200,256]
    {
        dim3 grid((LDIM + 127) / 128, HDIM, BDIM);
        attn_kernel<<<grid, 128>>>(qkv, ctx);
    }
    // 3) Out projection + bias + residual: y = ctx @ out_w^T + out_b + x
    {
        dim3 grid(EDIM / 64, (MROWS + 63) / 64);
        gemm_bias_kernel<true><<<grid, 256>>>(ctx, out_w, out_b, x, yy,
                                              MROWS, EDIM, EDIM);
    }
    // 4) LayerNorm -> d_out
    {
        ln_kernel<<<MROWS / 8, 256>>>(yy, ln_g, ln_b, out);
    }
}